// round 5
// baseline (speedup 1.0000x reference)
#include <cuda_runtime.h>

#define B_ 128
#define T_ 2048
#define D_ 128
#define H_ 512
#define L_ 10
#define NCTA 128

// shared-memory row strides (floats), padded to dodge bank conflicts
#define WH_LD 516
#define WI_LD 132
#define XS_LD 132
#define HS_LD 260
#define SM_WH (64 * WH_LD)
#define SM_WI (64 * WI_LD)
#define SM_XS (32 * XS_LD)
#define SM_HS (32 * HS_LD)
#define SMEM_FLOATS (SM_WH + SM_WI + SM_XS + SM_HS)
#define SMEM_BYTES (SMEM_FLOATS * 4)

// LSTM hidden state, layout [hidden_unit][batch] (coalesced over batch),
// double-buffered across timesteps. Cell state c lives in registers.
__device__ float g_h[2][H_ * B_];

// grid barrier state (reset by init kernel each launch -> deterministic replays)
__device__ unsigned g_bar_count;
__device__ volatile unsigned g_bar_flag;

__device__ __forceinline__ void cpa16(float* dst, const float* src) {
    unsigned d = (unsigned)__cvta_generic_to_shared(dst);
    asm volatile("cp.async.ca.shared.global [%0], [%1], 16;\n" ::"r"(d), "l"(src));
}

__global__ void init_state_kernel() {
    int i = blockIdx.x * blockDim.x + threadIdx.x;
    if (i < H_ * B_) {
        g_h[0][i] = 0.f;
        g_h[1][i] = 0.f;
    }
    if (i == 0) {
        g_bar_count = 0;
        g_bar_flag = 0;
    }
}

// NOTE: parameter names must not collide with float4 member names (x/y/z/w).
#define FMA4(acc, wv, hv)              \
    acc = fmaf((wv).x, (hv).x, acc);   \
    acc = fmaf((wv).y, (hv).y, acc);   \
    acc = fmaf((wv).z, (hv).z, acc);   \
    acc = fmaf((wv).w, (hv).w, acc);

// Accumulate gates over n4*4 contiguous K values.
__device__ __forceinline__ void accum_panel(
    const float* __restrict__ hsrc, int ld, int n4,
    const float* __restrict__ W, int wld, int koff,
    int b0, int b1, int u, float* acc0, float* acc1)
{
    const float4* h0p = (const float4*)(hsrc + b0 * ld);
    const float4* h1p = (const float4*)(hsrc + b1 * ld);
    const float* w0 = W + (0 * 16 + u) * wld + koff;
    const float* w1 = W + (1 * 16 + u) * wld + koff;
    const float* w2 = W + (2 * 16 + u) * wld + koff;
    const float* w3 = W + (3 * 16 + u) * wld + koff;
#pragma unroll 4
    for (int k4 = 0; k4 < n4; k4++) {
        float4 h0 = h0p[k4];
        float4 h1 = h1p[k4];
        float4 wa = *(const float4*)(w0 + k4 * 4);
        float4 wb = *(const float4*)(w1 + k4 * 4);
        float4 wc = *(const float4*)(w2 + k4 * 4);
        float4 wd = *(const float4*)(w3 + k4 * 4);
        FMA4(acc0[0], wa, h0); FMA4(acc1[0], wa, h1);
        FMA4(acc0[1], wb, h0); FMA4(acc1[1], wb, h1);
        FMA4(acc0[2], wc, h0); FMA4(acc1[2], wc, h1);
        FMA4(acc0[3], wd, h0); FMA4(acc1[3], wd, h1);
    }
}

// Persistent LSTM: 128 CTAs = (4 batch-chunks of 32) x (32 unit-chunks of 16),
// all co-resident (1 CTA/SM). Weights stay smem-resident for all T steps;
// cell state c stays in registers; one software grid barrier per step.
__global__ __launch_bounds__(256, 1) void lstm_persistent_kernel(
    const float* __restrict__ x,
    const float* __restrict__ Wih,
    const float* __restrict__ Whh,
    const float* __restrict__ bias)
{
    extern __shared__ float sm[];
    float* Wh = sm;                 // [64][WH_LD]
    float* Wi = Wh + SM_WH;         // [64][WI_LD]
    float* xs = Wi + SM_WI;         // [32][XS_LD]
    float* hs = xs + SM_XS;         // [32][HS_LD] (one 256-wide K panel)

    const int tid = threadIdx.x;
    const int bc = blockIdx.x & 3;        // batch chunk
    const int jc = blockIdx.x >> 2;       // unit chunk
    const int j0 = jc * 16;

    // ---- one-time weight loads (async) ----
    {
        // W_ih tile: 64 rows x 128 floats = 2048 float4, 8 per thread
#pragma unroll
        for (int r = 0; r < 8; r++) {
            int idx = tid + r * 256;
            int row = idx >> 5;
            int col = idx & 31;
            int grow = (row >> 4) * H_ + j0 + (row & 15);
            cpa16(Wi + row * WI_LD + col * 4, Wih + (size_t)grow * D_ + col * 4);
        }
        // W_hh tile: 64 rows x 512 floats = 8192 float4, 32 per thread
#pragma unroll
        for (int r = 0; r < 32; r++) {
            int idx = tid + r * 256;
            int row = idx >> 7;
            int col = idx & 127;
            int grow = (row >> 4) * H_ + j0 + (row & 15);
            cpa16(Wh + row * WH_LD + col * 4, Whh + (size_t)grow * H_ + col * 4);
        }
        asm volatile("cp.async.commit_group;\n");
    }

    const int bq = tid & 15;
    const int u = tid >> 4;                 // local unit 0..15
    const int b0 = bq, b1 = bq + 16;
    const int ug = j0 + u;

    const float bi = bias[0 * H_ + ug];
    const float bf = bias[1 * H_ + ug];
    const float bg = bias[2 * H_ + ug];
    const float bo = bias[3 * H_ + ug];

    float c0 = 0.f, c1 = 0.f;               // register-resident cell state

    asm volatile("cp.async.wait_group 0;\n");
    __syncthreads();

    for (int t = 0; t < T_; t++) {
        const int p = t & 1;
        const float* __restrict__ h_prev = g_h[p];
        float* __restrict__ h_next = g_h[p ^ 1];

        // ---- load x tile and h panel 0 ----
        {
            int b_l = tid >> 3;
            int d0 = (tid & 7) * 16;
            const float4* src = (const float4*)(x + ((size_t)(bc * 32 + b_l) * T_ + t) * D_ + d0);
            float4* dst = (float4*)(xs + b_l * XS_LD + d0);
            dst[0] = src[0]; dst[1] = src[1]; dst[2] = src[2]; dst[3] = src[3];
        }
#pragma unroll
        for (int r = 0; r < 8; r++) {
            int idx = tid + r * 256;
            int k_l = idx >> 3;
            int b4 = idx & 7;
            float4 v = *(const float4*)(h_prev + (size_t)k_l * B_ + bc * 32 + b4 * 4);
            hs[(b4 * 4 + 0) * HS_LD + k_l] = v.x;
            hs[(b4 * 4 + 1) * HS_LD + k_l] = v.y;
            hs[(b4 * 4 + 2) * HS_LD + k_l] = v.z;
            hs[(b4 * 4 + 3) * HS_LD + k_l] = v.w;
        }
        __syncthreads();

        float acc0[4] = {0.f, 0.f, 0.f, 0.f};
        float acc1[4] = {0.f, 0.f, 0.f, 0.f};

        // x-projection (K = 128) + recurrent panel 0 (K 0..255)
        accum_panel(xs, XS_LD, 32, Wi, WI_LD, 0, b0, b1, u, acc0, acc1);
        accum_panel(hs, HS_LD, 64, Wh, WH_LD, 0, b0, b1, u, acc0, acc1);

        __syncthreads();
        // load h panel 1 (K 256..511)
#pragma unroll
        for (int r = 0; r < 8; r++) {
            int idx = tid + r * 256;
            int k_l = idx >> 3;
            int b4 = idx & 7;
            float4 v = *(const float4*)(h_prev + (size_t)(256 + k_l) * B_ + bc * 32 + b4 * 4);
            hs[(b4 * 4 + 0) * HS_LD + k_l] = v.x;
            hs[(b4 * 4 + 1) * HS_LD + k_l] = v.y;
            hs[(b4 * 4 + 2) * HS_LD + k_l] = v.z;
            hs[(b4 * 4 + 3) * HS_LD + k_l] = v.w;
        }
        __syncthreads();

        accum_panel(hs, HS_LD, 64, Wh, WH_LD, 256, b0, b1, u, acc0, acc1);

        // ---- cell update (c in registers), write h_next ----
        {
            const float gi = acc0[0] + bi;
            const float gf = acc0[1] + bf;
            const float gg = acc0[2] + bg;
            const float go = acc0[3] + bo;
            const float si = 1.f / (1.f + expf(-gi));
            const float sf = 1.f / (1.f + expf(-gf));
            const float so = 1.f / (1.f + expf(-go));
            c0 = sf * c0 + si * tanhf(gg);
            h_next[(size_t)ug * B_ + bc * 32 + b0] = so * tanhf(c0);
        }
        {
            const float gi = acc1[0] + bi;
            const float gf = acc1[1] + bf;
            const float gg = acc1[2] + bg;
            const float go = acc1[3] + bo;
            const float si = 1.f / (1.f + expf(-gi));
            const float sf = 1.f / (1.f + expf(-gf));
            const float so = 1.f / (1.f + expf(-go));
            c1 = sf * c1 + si * tanhf(gg);
            h_next[(size_t)ug * B_ + bc * 32 + b1] = so * tanhf(c1);
        }

        // ---- grid barrier (epoch = t+1) ----
        __syncthreads();
        if (tid == 0) {
            __threadfence();
            unsigned arrived = atomicAdd(&g_bar_count, 1);
            if (arrived == NCTA - 1) {
                g_bar_count = 0;
                __threadfence();
                g_bar_flag = (unsigned)(t + 1);
            } else {
                while (g_bar_flag < (unsigned)(t + 1)) { }
                __threadfence();
            }
        }
        __syncthreads();
    }
}

// logits = h_final @ W_out^T, then softmax. h_final layout [k][b].
__global__ void final_softmax_kernel(const float* __restrict__ Wout,
                                     float* __restrict__ out, int p_final)
{
    __shared__ float ws[L_][H_];
    const int tid = threadIdx.x;  // 128 threads, one per batch
    const float* __restrict__ hf = g_h[p_final];
    for (int i = tid; i < L_ * H_; i += 128) ws[i / H_][i % H_] = Wout[i];
    __syncthreads();

    float acc[L_];
#pragma unroll
    for (int l = 0; l < L_; l++) acc[l] = 0.f;
    for (int k = 0; k < H_; k++) {
        float hv = hf[(size_t)k * B_ + tid];
#pragma unroll
        for (int l = 0; l < L_; l++) acc[l] = fmaf(ws[l][k], hv, acc[l]);
    }
    float m = acc[0];
#pragma unroll
    for (int l = 1; l < L_; l++) m = fmaxf(m, acc[l]);
    float ssum = 0.f;
#pragma unroll
    for (int l = 0; l < L_; l++) {
        acc[l] = expf(acc[l] - m);
        ssum += acc[l];
    }
    const float inv = 1.f / ssum;
#pragma unroll
    for (int l = 0; l < L_; l++) out[(size_t)tid * L_ + l] = acc[l] * inv;
}

extern "C" void kernel_launch(void* const* d_in, const int* in_sizes, int n_in,
                              void* d_out, int out_size)
{
    const float* x    = (const float*)d_in[0];
    const float* Wih  = (const float*)d_in[1];
    const float* Whh  = (const float*)d_in[2];
    const float* bias = (const float*)d_in[3];
    const float* Wout = (const float*)d_in[4];
    float* out = (float*)d_out;

    cudaFuncSetAttribute(lstm_persistent_kernel,
                         cudaFuncAttributeMaxDynamicSharedMemorySize, SMEM_BYTES);

    init_state_kernel<<<(H_ * B_ + 255) / 256, 256>>>();
    lstm_persistent_kernel<<<NCTA, 256, SMEM_BYTES>>>(x, Wih, Whh, bias);
    // after T steps (T even), final h lives in parity 0
    final_softmax_kernel<<<1, 128>>>(Wout, out, T_ & 1);
}

// round 7
// speedup vs baseline: 1.1933x; 1.1933x over previous
#include <cuda_runtime.h>

#define B_ 128
#define T_ 2048
#define D_ 128
#define H_ 512
#define L_ 10
#define NCTA 128

typedef unsigned long long u64;

// smem layout (floats):
//   wsm: [640 k][16 u][4 gates] pair-interleaved weights = 40960 floats (163840 B)
//   hsm: [512 k][32 b] h operand panel, stride 32        = 16384 floats (65536 B)
//   x panel aliases hsm rows 384..511 (16 KB), consumed before h rows 384..511 load
#define WSM_FLOATS (640 * 16 * 4)
#define HSM_FLOATS (512 * 32)
#define SMEM_FLOATS (WSM_FLOATS + HSM_FLOATS)
#define SMEM_BYTES (SMEM_FLOATS * 4)
#define XA_OFF (384 * 32)

// LSTM hidden state [unit][batch], double-buffered. Cell state c in registers.
__device__ float g_h[2][H_ * B_];

// grid barrier (reset each launch by init kernel -> deterministic replays)
__device__ unsigned g_bar_count;
__device__ volatile unsigned g_bar_flag;

__global__ void init_state_kernel() {
    int i = blockIdx.x * blockDim.x + threadIdx.x;
    if (i < H_ * B_) {
        g_h[0][i] = 0.f;
        g_h[1][i] = 0.f;
    }
    if (i == 0) {
        g_bar_count = 0;
        g_bar_flag = 0;
    }
}

// ---- packed f32x2 helpers (sm_103a FFMA2 path) ----
__device__ __forceinline__ u64 fma2(u64 a, u64 b, u64 c) {
    u64 d;
    asm("fma.rn.f32x2 %0, %1, %2, %3;" : "=l"(d) : "l"(a), "l"(b), "l"(c));
    return d;
}
__device__ __forceinline__ u64 splat2(float v) {
    u64 d;
    asm("mov.b64 %0, {%1, %1};" : "=l"(d) : "f"(v));
    return d;
}
__device__ __forceinline__ float2 u2f2(u64 d) {
    float2 r;
    asm("mov.b64 {%0, %1}, %2;" : "=f"(r.x), "=f"(r.y) : "l"(d));
    return r;
}

// Persistent LSTM. 128 CTAs = 4 batch-chunks(32) x 32 unit-chunks(16), 1 CTA/SM.
// Per thread: unit u = tid>>4, batch pair (2bq, 2bq+1), bq = tid&15; all 4 gates
// held as two packed f32x2 accumulators: (i,f) and (g,o).
__global__ __launch_bounds__(256, 1) void lstm_persistent_kernel(
    const float* __restrict__ x,
    const float* __restrict__ Wih,
    const float* __restrict__ Whh,
    const float* __restrict__ bias)
{
    extern __shared__ float sm[];
    float* wsm = sm;                    // pair-interleaved W
    float* hsm = sm + WSM_FLOATS;       // [k][32] h panel
    float* xa  = hsm + XA_OFF;          // x panel (aliases h rows 384..511)

    const int tid = threadIdx.x;
    const int bc = blockIdx.x & 3;      // batch chunk (32 batches)
    const int jc = blockIdx.x >> 2;     // unit chunk (16 units)
    const int j0 = jc * 16;

    // ---- one-time: build pair-interleaved weight tile ----
    // wsm[(k*16+u)*4 + g] = W_g[j0+u][k], k<512 from Whh, k>=512 from Wih(k-512)
    for (int i = tid; i < 640 * 64; i += 256) {
        int g = i & 3;
        int uu = (i >> 2) & 15;
        int k = i >> 6;
        int row = g * H_ + j0 + uu;
        float v = (k < 512) ? Whh[(size_t)row * H_ + k]
                            : Wih[(size_t)row * D_ + (k - 512)];
        wsm[(k * 16 + uu) * 4 + g] = v;
    }

    const int u = tid >> 4;             // 0..15
    const int bq = tid & 15;            // 0..15
    const int ug = j0 + u;
    const int bglob0 = bc * 32 + 2 * bq;

    const float bi = bias[0 * H_ + ug];
    const float bf = bias[1 * H_ + ug];
    const float bg = bias[2 * H_ + ug];
    const float bo = bias[3 * H_ + ug];

    float c0 = 0.f, c1 = 0.f;

    // ---- initial x prefetch (t=0): 16 scalars/thread, coalesced ----
    float xr[16];
#pragma unroll
    for (int r = 0; r < 16; r++) {
        int idx = tid + r * 256;
        int bl = idx >> 7;              // 0..31
        int kx = idx & 127;
        xr[r] = x[((size_t)(bc * 32 + bl) * T_ + 0) * D_ + kx];
    }

    __syncthreads();                    // weights ready

    for (int t = 0; t < T_; t++) {
        const int p = t & 1;
        const float* __restrict__ h_prev = g_h[p];
        float* __restrict__ h_next = g_h[p ^ 1];

        // ---- A: store x panel (k-rotated slot layout; 2-way STS worst case) ----
#pragma unroll
        for (int r = 0; r < 16; r++) {
            int idx = tid + r * 256;
            int bl = idx >> 7;
            int kx = idx & 127;
            int slot = ((bl >> 1) + kx) & 15;
            xa[kx * 32 + slot * 2 + (bl & 1)] = xr[r];
        }
        __syncthreads();

        // ---- B: x-projection (k = 512..639 of W), no h dependency ----
        u64 aif0, ago0, aif1, ago1;
        {
            u64 z = splat2(0.f);
            aif0 = z; ago0 = z; aif1 = z; ago1 = z;
        }
#pragma unroll 4
        for (int kx = 0; kx < 128; kx++) {
            int slot = (bq + kx) & 15;
            float2 hv = *(const float2*)(xa + kx * 32 + slot * 2);
            const u64* w = (const u64*)(wsm + ((512 + kx) * 16 + u) * 4);
            u64 h0 = splat2(hv.x);
            u64 h1 = splat2(hv.y);
            aif0 = fma2(w[0], h0, aif0);
            ago0 = fma2(w[1], h0, ago0);
            aif1 = fma2(w[0], h1, aif1);
            ago1 = fma2(w[1], h1, ago1);
        }

        // ---- C: grid-barrier wait (mostly hidden behind B) ----
        if (tid == 0) {
            while (g_bar_flag < (unsigned)t) { }
        }
        __syncthreads();                // also: x reads done before D overwrites xa

        // ---- D: h reload, [k][b] layout preserved (no transpose) ----
        {
            float4 stage[8];
#pragma unroll
            for (int r = 0; r < 8; r++) {
                int idx = tid + r * 256;
                int k = idx >> 3;
                int c = idx & 7;
                stage[r] = *(const float4*)(h_prev + (size_t)k * B_ + bc * 32 + c * 4);
            }
#pragma unroll
            for (int r = 0; r < 8; r++) {
                int idx = tid + r * 256;
                int k = idx >> 3;
                int c = idx & 7;
                *(float4*)(hsm + k * 32 + c * 4) = stage[r];
            }
#pragma unroll
            for (int r = 8; r < 16; r++) {
                int idx = tid + r * 256;
                int k = idx >> 3;
                int c = idx & 7;
                stage[r - 8] = *(const float4*)(h_prev + (size_t)k * B_ + bc * 32 + c * 4);
            }
#pragma unroll
            for (int r = 8; r < 16; r++) {
                int idx = tid + r * 256;
                int k = idx >> 3;
                int c = idx & 7;
                *(float4*)(hsm + k * 32 + c * 4) = stage[r - 8];
            }
        }
        __syncthreads();

        // ---- E: recurrent part, k = 0..511 ----
#pragma unroll 4
        for (int k = 0; k < 512; k++) {
            float2 hv = *(const float2*)(hsm + k * 32 + 2 * bq);
            const u64* w = (const u64*)(wsm + (k * 16 + u) * 4);
            u64 h0 = splat2(hv.x);
            u64 h1 = splat2(hv.y);
            aif0 = fma2(w[0], h0, aif0);
            ago0 = fma2(w[1], h0, ago0);
            aif1 = fma2(w[0], h1, aif1);
            ago1 = fma2(w[1], h1, ago1);
        }

        // ---- F: cell update (c in regs), h_next store ----
        float h0v, h1v;
        {
            float2 vif = u2f2(aif0);
            float2 vgo = u2f2(ago0);
            const float gi = vif.x + bi;
            const float gf = vif.y + bf;
            const float gg = vgo.x + bg;
            const float go_ = vgo.y + bo;
            const float si = 1.f / (1.f + expf(-gi));
            const float sf = 1.f / (1.f + expf(-gf));
            const float so = 1.f / (1.f + expf(-go_));
            c0 = sf * c0 + si * tanhf(gg);
            h0v = so * tanhf(c0);
        }
        {
            float2 vif = u2f2(aif1);
            float2 vgo = u2f2(ago1);
            const float gi = vif.x + bi;
            const float gf = vif.y + bf;
            const float gg = vgo.x + bg;
            const float go_ = vgo.y + bo;
            const float si = 1.f / (1.f + expf(-gi));
            const float sf = 1.f / (1.f + expf(-gf));
            const float so = 1.f / (1.f + expf(-go_));
            c1 = sf * c1 + si * tanhf(gg);
            h1v = so * tanhf(c1);
        }
        *(float2*)(h_next + (size_t)ug * B_ + bglob0) = make_float2(h0v, h1v);

        // ---- G: arrive (non-blocking) + x prefetch for t+1 ----
        __syncthreads();                // all CTA stores issued before arrive
        if (tid == 0) {
            __threadfence();
            if (atomicAdd(&g_bar_count, 1) == NCTA - 1) {
                g_bar_count = 0;
                __threadfence();
                g_bar_flag = (unsigned)(t + 1);
            }
        }
        {
            const int tt = (t + 1 < T_) ? (t + 1) : t;
#pragma unroll
            for (int r = 0; r < 16; r++) {
                int idx = tid + r * 256;
                int bl = idx >> 7;
                int kx = idx & 127;
                xr[r] = x[((size_t)(bc * 32 + bl) * T_ + tt) * D_ + kx];
            }
        }
        // next iter's x STS is safe: all threads passed E before the sync above
    }
}

// logits = h_final @ W_out^T, then softmax. h_final layout [u][b].
__global__ void final_softmax_kernel(const float* __restrict__ Wout,
                                     float* __restrict__ out, int p_final)
{
    __shared__ float ws[L_][H_];
    const int tid = threadIdx.x;  // 128 threads, one per batch
    const float* __restrict__ hf = g_h[p_final];
    for (int i = tid; i < L_ * H_; i += 128) ws[i / H_][i % H_] = Wout[i];
    __syncthreads();

    float acc[L_];
#pragma unroll
    for (int l = 0; l < L_; l++) acc[l] = 0.f;
    for (int k = 0; k < H_; k++) {
        float hv = hf[(size_t)k * B_ + tid];
#pragma unroll
        for (int l = 0; l < L_; l++) acc[l] = fmaf(ws[l][k], hv, acc[l]);
    }
    float m = acc[0];
#pragma unroll
    for (int l = 1; l < L_; l++) m = fmaxf(m, acc[l]);
    float ssum = 0.f;
#pragma unroll
    for (int l = 0; l < L_; l++) {
        acc[l] = expf(acc[l] - m);
        ssum += acc[l];
    }
    const float inv = 1.f / ssum;
#pragma unroll
    for (int l = 0; l < L_; l++) out[(size_t)tid * L_ + l] = acc[l] * inv;
}

extern "C" void kernel_launch(void* const* d_in, const int* in_sizes, int n_in,
                              void* d_out, int out_size)
{
    const float* x    = (const float*)d_in[0];
    const float* Wih  = (const float*)d_in[1];
    const float* Whh  = (const float*)d_in[2];
    const float* bias = (const float*)d_in[3];
    const float* Wout = (const float*)d_in[4];
    float* out = (float*)d_out;

    cudaFuncSetAttribute(lstm_persistent_kernel,
                         cudaFuncAttributeMaxDynamicSharedMemorySize, SMEM_BYTES);

    init_state_kernel<<<(H_ * B_ + 255) / 256, 256>>>();
    lstm_persistent_kernel<<<NCTA, 256, SMEM_BYTES>>>(x, Wih, Whh, bias);
    // after T steps (T even), final h lives in parity 0
    final_softmax_kernel<<<1, 128>>>(Wout, out, T_ & 1);
}